// round 15
// baseline (speedup 1.0000x reference)
#include <cuda_runtime.h>
#include <cuda_bf16.h>

#define NCTA 128
#define TPB  512
#define FPITERS 1
#define NIN0 10
#define NIN1 8
#define MAXSWEEP 5
#define NROUNDS (63*MAXSWEEP)

// ---------------- device scratch (no allocation allowed) ----------------
__device__ __align__(16) float g_qf[4096];   // mask; later Z
__device__ __align__(16) float g_StS[4096];  // StS; later G (row-major)
__device__ __align__(16) float g_b[4096];    // rhs; later M
__device__ __align__(16) float g_x[4096];
__device__ __align__(16) float g_y[4096];    // matvec y; later Y
__device__ float g_sv[64];
__device__ float g_fs[64];
__device__ int g_cnt = 0;
__device__ int g_gen = 0;    // 128-CTA barrier (monotone gen; replay-safe)
__device__ int g_cnt8 = 0;
__device__ int g_gen8 = 0;   // 8-CTA barrier for the epilogue

__device__ __forceinline__ void gbar_n(int n, int* cnt, int* gen) {
    __threadfence();
    __syncthreads();
    if (threadIdx.x == 0) {
        int my = *(volatile int*)gen;
        int old = atomicAdd(cnt, 1);
        if (old == n - 1) {
            *cnt = 0;
            __threadfence();
            atomicAdd(gen, 1);
        } else {
            while (*(volatile int*)gen == my) { }
        }
    }
    __syncthreads();
    __threadfence();
}
__device__ __forceinline__ void gbar()  { gbar_n(NCTA, &g_cnt,  &g_gen);  }
__device__ __forceinline__ void gbar8() { gbar_n(8,    &g_cnt8, &g_gen8); }

struct SolveSm {
    float Ms[64*65];
    float xs[4096];
    float zs[2][64];
};
struct FinalSm {
    float Gf[64*68];            // column j at Gf[j*68+r]; 17 float4/column
    float4 bufp[2][16][16];     // cross-warp p-column exchange (parity, warp, kk)
    float4 bufq[2][16][16];     // cross-warp q-column exchange
    float nbp[2][16];
    float nbq[2][16];
    float sarr[64];
    float thr_s;
};
union __align__(16) Smem { SolveSm s; FinalSm f; };

__global__ void __launch_bounds__(TPB, 1)
k_all(const float* __restrict__ inp, const float* __restrict__ L,
      const void* __restrict__ mask, const float* __restrict__ D,
      const float* __restrict__ thP, const float* __restrict__ vp,
      const float* __restrict__ netap, const float* __restrict__ lam1p,
      const float* __restrict__ lam2p, const float* __restrict__ rhop,
      const float* __restrict__ S, float* __restrict__ out) {
    __shared__ Smem sm;
    __shared__ int s_badU8, s_off1;
    int t = threadIdx.x;
    int cta = blockIdx.x;

    // ================= phase 0: prep (CTA0), StS (CTA1-4) =====================
    if (cta == 0) {
        if (t == 0) { s_badU8 = 0; s_off1 = 0; }
        __syncthreads();
        const unsigned char* m8 = (const unsigned char*)mask;
        int b1 = 0, b2 = 0;
        for (int i = t; i < 4096; i += TPB) {
            unsigned v = m8[i];
            if (v > 1u) b1 = 1;
            if (v == 1u && (i & 3) != 0) b2 = 1;
        }
        if (b1) s_badU8 = 1;
        if (b2) s_off1 = 1;
        __syncthreads();
        int mode = s_badU8 ? 1 : (s_off1 ? 0 : 2);   // 0=u8,1=f32,2=i32
        float rho = *rhop;
        for (int i = t; i < 4096; i += TPB) {
            bool on;
            if (mode == 0)      on = ((const unsigned char*)mask)[i] != 0;
            else if (mode == 1) on = ((const float*)mask)[i] != 0.0f;
            else                on = ((const int*)mask)[i] != 0;
            g_qf[i] = on ? 1.0f : 0.0f;
            g_b[i]  = rho * (L[i] - thP[i]) + (on ? inp[i] : 0.0f);
        }
    } else if (cta <= 4) {
        for (int i = t; i < 4096; i += TPB) { int h = i >> 6, a = i & 63; sm.s.Ms[h*65 + a] = S[i]; }
        __syncthreads();
        int base = (cta - 1) * 1024;
        #pragma unroll
        for (int k = 0; k < 2; k++) {
            int idx = base + t + k*TPB;
            int a = idx >> 6, b = idx & 63;
            float acc = 0.0f;
            #pragma unroll 16
            for (int h = 0; h < 64; h++) acc += sm.s.Ms[h*65 + a] * sm.s.Ms[h*65 + b];
            g_StS[idx] = acc;
        }
    }
    gbar();   // 1

    float lam1 = *lam1p, lam2 = *lam2p, rho = *rhop;

    if (cta < 64) {
        for (int i = t; i < 4096; i += TPB) { int a = i >> 6, c = i & 63; sm.s.Ms[a*65 + c] = g_StS[i]; }
        __syncthreads();
    }

    // ---------------- apply: x_h = B_h^{-1} r_h (Jacobi, 64 threads/CTA) -------
    auto apply = [&](int useY, int nin) {
        if (cta < 64 && t < 64) {
            int h = cta, u = t;
            float r = g_b[h*64 + u];
            if (useY) r -= lam1 * g_y[h*64 + u];
            float Muu  = sm.s.Ms[u*65 + u];
            float dinv = 1.0f / (rho + g_qf[h*64 + u] + lam2 * Muu);
            float z = useY ? g_x[h*64 + u] : r * dinv;
            int cur = 0;
            sm.s.zs[0][u] = z;
            asm volatile("bar.sync 1, 64;" ::: "memory");
            for (int it = 0; it < nin; it++) {
                float a0=0.f,a1=0.f,a2=0.f,a3=0.f;
                const float* Mr = &sm.s.Ms[u*65];
                const float* zc = sm.s.zs[cur];
                #pragma unroll 16
                for (int c = 0; c < 64; c += 4) {
                    a0 += Mr[c]   * zc[c];
                    a1 += Mr[c+1] * zc[c+1];
                    a2 += Mr[c+2] * zc[c+2];
                    a3 += Mr[c+3] * zc[c+3];
                }
                float acc = (a0+a1) + (a2+a3);
                z = (r - lam2 * (acc - Muu * z)) * dinv;
                if (it + 1 < nin) {
                    sm.s.zs[cur^1][u] = z;
                    asm volatile("bar.sync 1, 64;" ::: "memory");
                    cur ^= 1;
                }
            }
            g_x[h*64 + u] = z;
        }
    };

    // ---------------- matvec: y = D x (all 128 CTAs, HBM-streaming) -----------
    auto matvec = [&]() {
        const float4* x4 = (const float4*)g_x;
        float4* xs4 = (float4*)sm.s.xs;
        for (int i = t; i < 1024; i += TPB) xs4[i] = x4[i];
        __syncthreads();
        int w = t >> 5, lane = t & 31;
        int row0 = cta * 32 + w * 2;
        #pragma unroll
        for (int rr = 0; rr < 2; rr++) {
            int row = row0 + rr;
            const float4* D4 = (const float4*)(D + (size_t)row * 4096);
            float acc = 0.0f;
            #pragma unroll
            for (int it = 0; it < 32; it++) {
                float4 d  = D4[lane + 32*it];
                float4 xv = xs4[lane + 32*it];
                acc += d.x*xv.x + d.y*xv.y + d.z*xv.z + d.w*xv.w;
            }
            #pragma unroll
            for (int off = 16; off > 0; off >>= 1)
                acc += __shfl_xor_sync(0xffffffffu, acc, off);
            if (lane == 0) g_y[row] = acc;
        }
        __syncthreads();
    };

    apply(0, NIN0);
    gbar();   // 2
    for (int it = 0; it < FPITERS; it++) {
        matvec();
        gbar();
        apply(1, NIN1);
        gbar();
    }

    // CTAs 8..127: remaining work uses 8 CTAs; exit now.
    if (cta >= 8) return;

    // ========== register-resident systolic Jacobi SVD on CTA0 =================
    if (cta == 0) {
        float* Gf = sm.f.Gf;
        float4* Gc = (float4*)sm.f.Gf;
        int lane = t & 31, w = t >> 5;
        int grp = lane >> 4, kk = lane & 15;
        int k = (w << 1) | grp;              // pair id 0..31

        // stage X into Gf (column-major float4 blocks)
        for (int i = t; i < 4096; i += TPB) {
            int r = i >> 6, j = i & 63;
            Gf[j*68 + r] = g_x[i] + thP[i];
        }
        __syncthreads();

        // initial columns into registers; pair0=(63,0), pair k=(k, 63-k)
        int pc = (k == 0) ? 63 : k;
        int qc = (k == 0) ? 0  : 63 - k;
        float4 P = Gc[pc*17 + kk];
        float4 Q = Gc[qc*17 + kk];
        float npp = P.x*P.x + P.y*P.y + P.z*P.z + P.w*P.w;
        float nqq = Q.x*Q.x + Q.y*Q.y + Q.z*Q.z + Q.w*Q.w;
        #pragma unroll
        for (int o = 8; o; o >>= 1) {
            npp += __shfl_xor_sync(0xffffffffu, npp, o);
            nqq += __shfl_xor_sync(0xffffffffu, nqq, o);
        }
        __syncthreads();   // Gf staging reads complete

        // 315 rounds; exchange topology: p flows k+1->k, q flows k-1->k;
        // pair0.p fixed (col 63); pair31.p_new = own q_old.
        // Intra-warp halves exchange via one shfl.xor(16); cross-warp via
        // parity-double-buffered smem (one CTA barrier per round).
        for (int r = 0; r < NROUNDS; r++) {
            float dp = P.x*Q.x + P.y*Q.y + P.z*Q.z + P.w*Q.w;
            #pragma unroll
            for (int o = 8; o; o >>= 1) dp += __shfl_xor_sync(0xffffffffu, dp, o);
            float dpg = copysignf(fmaxf(fabsf(dp), 1e-30f), dp);
            float zeta = __fdividef(nqq - npp, 2.0f * dpg);
            float tt = copysignf(__fdividef(1.0f, fabsf(zeta) + __fsqrt_rn(1.0f + zeta*zeta)), zeta);
            float c = __frsqrt_rn(1.0f + tt*tt), s = tt * c;
            float4 nP, nQ;
            nP.x = c*P.x - s*Q.x;  nQ.x = s*P.x + c*Q.x;
            nP.y = c*P.y - s*Q.y;  nQ.y = s*P.y + c*Q.y;
            nP.z = c*P.z - s*Q.z;  nQ.z = s*P.z + c*Q.z;
            nP.w = c*P.w - s*Q.w;  nQ.w = s*P.w + c*Q.w;
            float nppn = npp - tt*dpg, nqqn = nqq + tt*dpg;
            int pb = r & 1;
            // cross-warp sends: g0 sends nP backward, g1 sends nQ forward
            if (grp == 0) {
                if (w > 0) {
                    sm.f.bufp[pb][w][kk] = nP;
                    if (kk == 0) sm.f.nbp[pb][w] = nppn;
                }
            } else {
                if (w < 15) {
                    sm.f.bufq[pb][w][kk] = nQ;
                    if (kk == 0) sm.f.nbq[pb][w] = nqqn;
                }
            }
            // intra-warp exchange: g0 sends nQ, g1 sends nP
            float4 sv4; sv4.x = grp ? nP.x : nQ.x; sv4.y = grp ? nP.y : nQ.y;
            sv4.z = grp ? nP.z : nQ.z; sv4.w = grp ? nP.w : nQ.w;
            float4 sh;
            sh.x = __shfl_xor_sync(0xffffffffu, sv4.x, 16);
            sh.y = __shfl_xor_sync(0xffffffffu, sv4.y, 16);
            sh.z = __shfl_xor_sync(0xffffffffu, sv4.z, 16);
            sh.w = __shfl_xor_sync(0xffffffffu, sv4.w, 16);
            float nsh = __shfl_xor_sync(0xffffffffu, grp ? nppn : nqqn, 16);
            __syncthreads();
            if (grp == 0) {
                float4 rd = sm.f.bufq[pb][(w > 0 ? w-1 : 0)][kk];
                float nrd = sm.f.nbq[pb][(w > 0 ? w-1 : 0)];
                if (w == 0) { P = nP; npp = nppn; Q = sh; nqq = nsh; }
                else        { P = sh; npp = nsh;  Q = rd; nqq = nrd; }
            } else {
                float4 rd = sm.f.bufp[pb][(w < 15 ? w+1 : 15)][kk];
                float nrd = sm.f.nbp[pb][(w < 15 ? w+1 : 15)];
                if (w == 15) { P = nQ; npp = nqqn; }
                else         { P = rd; npp = nrd; }
                Q = sh; nqq = nsh;
            }
        }
        // 315 % 63 == 0 -> columns back at initial indices; dump to Gf
        Gc[pc*17 + kk] = P;
        Gc[qc*17 + kk] = Q;
        __syncthreads();

        // singular values + threshold + spectral factors
        if (t < 64) {
            float acc = 0.0f;
            #pragma unroll 16
            for (int r = 0; r < 64; r++) { float g = Gf[t*68 + r]; acc += g*g; }
            sm.f.sarr[t] = sqrtf(acc);
        }
        __syncthreads();
        if (t == 0) {
            float m = 0.0f;
            for (int j = 0; j < 64; j++) m = fmaxf(m, sm.f.sarr[j]);
            float vv = *vp;
            float tau = 0.4f / (1.0f + expf(-vv));
            sm.f.thr_s = tau * m;
        }
        __syncthreads();
        if (t < 64) {
            float s = sm.f.sarr[t];
            float st = s - sm.f.thr_s;
            g_sv[t] = s;
            g_fs[t] = (st > 0.0f) ? st / (s*s*s) : 0.0f;
        }
        // dump G row-major into dead g_StS
        for (int i = t; i < 4096; i += TPB) {
            int r = i >> 6, j = i & 63;
            g_StS[i] = Gf[j*68 + r];
        }
    }
    gbar8();   // Jacobi results visible to CTAs 0-7

    // ======= parallel DK epilogue: Ltmp = G M G^T X, M = DK(w, N) =============
    float neta = *netap;
    int idx = cta * TPB + t;

    // Phase A: Y[i][c] = sum_r G[r][i] X[r][c]; N -> M
    {
        int i = idx >> 6, c = idx & 63;
        float accY = 0.0f, accN = 0.0f;
        #pragma unroll 8
        for (int r = 0; r < 64; r++) {
            float gri = g_StS[r*64 + i];
            accY += gri * (g_x[r*64 + c] + thP[r*64 + c]);
            accN += gri * g_StS[r*64 + c];
        }
        g_y[idx] = accY;
        float Mv;
        if (i == c) Mv = g_fs[i];
        else {
            float si = g_sv[i], sj = g_sv[c];
            float ni = si*si, nj = sj*sj, dn = nj - ni;
            Mv = (fabsf(dn) > 1e-6f*(ni + nj) + 1e-30f)
                 ? accN * (g_fs[c] - g_fs[i]) / dn : 0.0f;
        }
        g_b[idx] = Mv;
    }
    gbar8();

    // Phase B: Z[i][c] = sum_m M[i][m] Y[m][c]
    {
        int i = idx >> 6, c = idx & 63;
        float acc = 0.0f;
        #pragma unroll 8
        for (int m = 0; m < 64; m++) acc += g_b[i*64 + m] * g_y[m*64 + c];
        g_qf[idx] = acc;
    }
    gbar8();

    // Phase C: Ltmp = G Z ; Ptmp = thP + neta*(x - Ltmp)
    {
        int r = idx >> 6, c = idx & 63;
        float acc = 0.0f;
        #pragma unroll 8
        for (int j = 0; j < 64; j++) acc += g_StS[r*64 + j] * g_qf[j*64 + c];
        out[idx]        = acc;
        out[4096 + idx] = thP[idx] + neta * (g_x[idx] - acc);
    }
}

// ---------------- launch ----------------
extern "C" void kernel_launch(void* const* d_in, const int* in_sizes, int n_in,
                              void* d_out, int out_size) {
    const float* inp  = (const float*)d_in[0];
    const float* L    = (const float*)d_in[1];
    const void*  mask = d_in[2];
    const float* D    = (const float*)d_in[3];
    const float* thP  = (const float*)d_in[4];
    const float* v    = (const float*)d_in[5];
    const float* neta = (const float*)d_in[6];
    const float* lam1 = (const float*)d_in[7];
    const float* lam2 = (const float*)d_in[8];
    const float* rho  = (const float*)d_in[9];
    const float* S    = (const float*)d_in[10];
    float* out = (float*)d_out;

    k_all<<<NCTA, TPB>>>(inp, L, mask, D, thP, v, neta, lam1, lam2, rho, S, out);
}